// round 5
// baseline (speedup 1.0000x reference)
#include <cuda_runtime.h>
#include <cuda_fp16.h>
#include <cstddef>

// Problem constants: B=2, H=16, T=2048, C=64
#define T_SEQ   2048
#define CDIM    64
#define HEADS   16
#define BATCH   2
#define M_TILE  16
#define KTILE   64
#define NTILES  (T_SEQ/KTILE)      // 32
#define THREADS 256
#define KSTR4   17                 // float4 stride of staging rows (68 floats)
#define SSTRH   2064               // halves per scores row (2048 + 16 pad)

// smem floats:
//   ks   : 2 * 64*68 = 8704      (double-buffered K/V staging)
//   qs   : 16*68     = 1088
//   red  : 16*64     = 1024
//   rinv : 16
//   scores(half): 16*2064 halves = 16512 floats
// total = 27344 floats = 109,376 B  -> 2 CTAs per SM
#define KS_FLOATS   (KTILE*68)
#define OFF_QS      (2*KS_FLOATS)
#define OFF_RED     (OFF_QS + M_TILE*68)
#define OFF_RINV    (OFF_RED + 16*64)
#define OFF_SCO     (OFF_RINV + 16)
#define SMEM_FLOATS (OFF_SCO + (M_TILE*SSTRH)/2)

typedef unsigned long long u64;

#define FMA2(d, a, b) asm("fma.rn.f32x2 %0, %1, %2, %0;" : "+l"(d) : "l"(a), "l"(b))
#define UNPACK2(lo, hi, p) asm("mov.b64 {%0, %1}, %2;" : "=f"(lo), "=f"(hi) : "l"(p))
#define PACKDUP(d, s) asm("mov.b64 %0, {%1, %1};" : "=l"(d) : "f"(s))
#define CP_COMMIT()  asm volatile("cp.async.commit_group;" ::: "memory")
#define CP_WAIT1()   asm volatile("cp.async.wait_group 1;" ::: "memory")
#define CP_WAIT0()   asm volatile("cp.async.wait_group 0;" ::: "memory")

__device__ __forceinline__ void cp16(void* smem_dst, const void* gsrc) {
    unsigned saddr = (unsigned)__cvta_generic_to_shared(smem_dst);
    asm volatile("cp.async.cg.shared.global [%0], [%1], 16;" :: "r"(saddr), "l"(gsrc) : "memory");
}

// stage one 64x64 fp32 tile (K or V) into buffer buf via cp.async
__device__ __forceinline__ void stage_tile(float* ks, int buf, const float4* g4,
                                           int tile, int t) {
    float4* dst = (float4*)(ks + buf * KS_FLOATS);
    const float4* src = g4 + tile * (KTILE * CDIM / 4);
    #pragma unroll
    for (int i = 0; i < (KTILE * CDIM / 4) / THREADS; i++) {   // 4
        int idx = t + i * THREADS;
        int row = idx >> 4, c4 = idx & 15;
        cp16(&dst[row * KSTR4 + c4], &src[idx]);
    }
}

__global__ __launch_bounds__(THREADS, 2)
void sdpa_kernel(const float* __restrict__ q,
                 const float* __restrict__ k,
                 const float* __restrict__ v,
                 const int*   __restrict__ mask,
                 float* __restrict__ out,
                 float* __restrict__ attn)
{
    extern __shared__ float sm[];
    float*  ks       = sm;
    float*  qs       = sm + OFF_QS;
    float*  red      = sm + OFF_RED;
    float*  rinv     = sm + OFF_RINV;
    __half* scores_h = (__half*)(sm + OFF_SCO);
    __half2* sh2     = (__half2*)scores_h;

    const int t  = threadIdx.x;
    const int m0 = blockIdx.x * M_TILE;
    const int h  = blockIdx.y;
    const int b  = blockIdx.z;
    const int bh = b * HEADS + h;

    const float*  qg  = q + ((size_t)bh * T_SEQ + m0) * CDIM;
    const float4* kg4 = (const float4*)(k + (size_t)bh * T_SEQ * CDIM);
    const float4* vg4 = (const float4*)(v + (size_t)bh * T_SEQ * CDIM);
    const int*    mg  = mask + ((size_t)b * T_SEQ + m0) * T_SEQ;
    float* attng = attn + ((size_t)bh * T_SEQ + m0) * T_SEQ;
    float* outg  = out  + ((size_t)bh * T_SEQ + m0) * CDIM;

    const ulonglong2* qs2 = (const ulonglong2*)qs;

    // prologue: prefetch K tiles 0,1
    stage_tile(ks, 0, kg4, 0, t); CP_COMMIT();
    stage_tile(ks, 1, kg4, 1, t); CP_COMMIT();

    // load Q tile (scaled by 1/8): 256 float4, one per thread
    {
        int row = t >> 4, c4 = t & 15;
        float4 qv = ((const float4*)qg)[row * 16 + c4];
        qv.x *= 0.125f; qv.y *= 0.125f; qv.z *= 0.125f; qv.w *= 0.125f;
        ((float4*)qs)[row * KSTR4 + c4] = qv;
    }

    // ============ Phase A: S = (Q/8)K^T fused mask+exp+rowsum ============
    // jt = t&63 -> one j per tile; g = t>>6 -> rows g, g+4, g+8, g+12
    const int jt = t & 63;
    const int g  = t >> 6;
    float rsum[4] = {0.f, 0.f, 0.f, 0.f};

    #pragma unroll 1
    for (int kt = 0; kt < NTILES; kt++) {
        const int j0 = kt * KTILE;
        int mreg[4];
        #pragma unroll
        for (int u = 0; u < 4; u++)
            mreg[u] = mg[(g + 4*u) * T_SEQ + j0 + jt];
        if (kt < NTILES - 1) CP_WAIT1(); else CP_WAIT0();
        __syncthreads();

        const ulonglong2* kb = (const ulonglong2*)(ks + (kt & 1) * KS_FLOATS);
        u64 acc[4] = {0ull, 0ull, 0ull, 0ull};

        #pragma unroll
        for (int c4 = 0; c4 < 16; c4++) {
            ulonglong2 kv = kb[jt * KSTR4 + c4];
            #pragma unroll
            for (int u = 0; u < 4; u++) {
                ulonglong2 qv = qs2[(g + 4*u) * KSTR4 + c4];   // warp broadcast
                FMA2(acc[u], qv.x, kv.x);
                FMA2(acc[u], qv.y, kv.y);
            }
        }
        __syncthreads();
        if (kt + 2 < NTILES) { stage_tile(ks, kt & 1, kg4, kt + 2, t); CP_COMMIT(); }

        #pragma unroll
        for (int u = 0; u < 4; u++) {
            float lo, hi; UNPACK2(lo, hi, acc[u]);
            float e = mreg[u] ? __expf(lo + hi) : 0.f;
            scores_h[(g + 4*u) * SSTRH + j0 + jt] = __float2half_rn(e);
            rsum[u] += e;
        }
    }

    // prefetch V tiles 0,1
    stage_tile(ks, 0, vg4, 0, t); CP_COMMIT();
    stage_tile(ks, 1, vg4, 1, t); CP_COMMIT();

    // rowsum partials + reduce
    #pragma unroll
    for (int u = 0; u < 4; u++) red[(g + 4*u) * 64 + jt] = rsum[u];
    __syncthreads();
    {
        int w = t >> 5, lane = t & 31;
        #pragma unroll
        for (int rr = 0; rr < 2; rr++) {
            int row = 2*w + rr;
            float s = red[row*64 + lane] + red[row*64 + 32 + lane];
            #pragma unroll
            for (int o = 16; o > 0; o >>= 1) s += __shfl_xor_sync(0xffffffffu, s, o);
            if (lane == 0) rinv[row] = 1.0f / s;
        }
    }
    __syncthreads();

    // write normalized attn (fp32) from half scores — overlaps V prefetch
    {
        float4* a4 = (float4*)attng;
        #pragma unroll 4
        for (int i = 0; i < (M_TILE * T_SEQ / 4) / THREADS; i++) {   // 32
            int idx = t + i * THREADS;
            int r = idx >> 9, c4 = idx & 511;
            float ri = rinv[r];
            float2 fa = __half22float2(sh2[r * (SSTRH/2) + 2*c4]);
            float2 fb = __half22float2(sh2[r * (SSTRH/2) + 2*c4 + 1]);
            float4 o = { fa.x*ri, fa.y*ri, fb.x*ri, fb.y*ri };
            a4[r * 512 + c4] = o;
        }
    }

    // ============ Phase B: out = P_unnorm @ V (scaled by rinv) ============
    // jg = t>>4 (4 j per tile); rb = t&1 (rows rb,rb+2..rb+14); cg = (t>>1)&7 (c4 cg, cg+8)
    const int jg = t >> 4;
    const int rb = t & 1;
    const int cg = (t >> 1) & 7;
    u64 acc[8][2][2];
    #pragma unroll
    for (int u = 0; u < 8; u++)
        #pragma unroll
        for (int w = 0; w < 2; w++) { acc[u][w][0] = 0ull; acc[u][w][1] = 0ull; }

    #pragma unroll 1
    for (int vt = 0; vt < NTILES; vt++) {
        if (vt < NTILES - 1) CP_WAIT1(); else CP_WAIT0();
        __syncthreads();
        const ulonglong2* vb = (const ulonglong2*)(ks + (vt & 1) * KS_FLOATS);

        #pragma unroll
        for (int jj = 0; jj < 4; jj++) {
            int jl = jg * 4 + jj;
            int j  = vt * KTILE + jl;
            ulonglong2 vv0 = vb[jl * KSTR4 + cg];
            ulonglong2 vv1 = vb[jl * KSTR4 + cg + 8];
            #pragma unroll
            for (int u = 0; u < 8; u++) {
                float p = __half2float(scores_h[(rb + 2*u) * SSTRH + j]);
                u64 pp; PACKDUP(pp, p);
                FMA2(acc[u][0][0], pp, vv0.x);
                FMA2(acc[u][0][1], pp, vv0.y);
                FMA2(acc[u][1][0], pp, vv1.x);
                FMA2(acc[u][1][1], pp, vv1.y);
            }
        }
        __syncthreads();
        if (vt + 2 < NTILES) { stage_tile(ks, vt & 1, vg4, vt + 2, t); CP_COMMIT(); }
    }

    // cross-jg reduction: reuse scores region (64 KB part <= 66 KB region)
    float4* part = (float4*)scores_h;
    #pragma unroll
    for (int u = 0; u < 8; u++) {
        int row = rb + 2*u;
        #pragma unroll
        for (int w = 0; w < 2; w++) {
            float4 f;
            UNPACK2(f.x, f.y, acc[u][w][0]);
            UNPACK2(f.z, f.w, acc[u][w][1]);
            part[(jg * 16 + row) * 16 + cg + 8*w] = f;
        }
    }
    __syncthreads();

    // 16 rows x 16 c4 = 256 float4: one per thread
    {
        float4* o4 = (float4*)outg;
        int row = t >> 4, c4 = t & 15;
        float4 s = {0.f, 0.f, 0.f, 0.f};
        #pragma unroll
        for (int gg = 0; gg < 16; gg++) {
            float4 p = part[(gg * 16 + row) * 16 + c4];
            s.x += p.x; s.y += p.y; s.z += p.z; s.w += p.w;
        }
        float ri = rinv[row];
        s.x *= ri; s.y *= ri; s.z *= ri; s.w *= ri;
        o4[row * 16 + c4] = s;
    }
}

extern "C" void kernel_launch(void* const* d_in, const int* in_sizes, int n_in,
                              void* d_out, int out_size)
{
    const float* q    = (const float*)d_in[0];
    const float* k    = (const float*)d_in[1];
    const float* v    = (const float*)d_in[2];
    const int*   mask = (const int*)d_in[3];

    float* out  = (float*)d_out;                                   // [B,H,T,C]
    float* attn = out + (size_t)BATCH * HEADS * T_SEQ * CDIM;      // [B,H,T,T]

    const size_t smem_bytes = (size_t)SMEM_FLOATS * sizeof(float); // 109,376 B
    cudaFuncSetAttribute(sdpa_kernel,
                         cudaFuncAttributeMaxDynamicSharedMemorySize,
                         (int)smem_bytes);

    dim3 grid(T_SEQ / M_TILE, HEADS, BATCH);   // (128, 16, 2)
    sdpa_kernel<<<grid, THREADS, smem_bytes>>>(q, k, v, mask, out, attn);
}

// round 6
// speedup vs baseline: 2.1376x; 2.1376x over previous
#include <cuda_runtime.h>
#include <cuda_fp16.h>
#include <cstddef>

// Problem: B=2, H=16, T=2048, C=64
#define T_SEQ   2048
#define CDIM    64
#define HEADS   16
#define BATCH   2
#define M_TILE  32
#define KTILE   128
#define ROUNDS  (T_SEQ/KTILE)    // 16
#define THREADS 512
#define KVSTR   72               // halves per staged K/V row (pad: conflict-free ldmatrix)
#define SSTR    2056             // halves per scores row (pad: conflict-free ldmatrix)

#define KVBUF_BYTES (KTILE*KVSTR*2)          // 18432
#define OFF_QH      (4*KVBUF_BYTES)          // 73728
#define OFF_RED     (OFF_QH + M_TILE*KVSTR*2)// 78336
#define OFF_RINV    (OFF_RED + 8*32*4)       // 79360
#define OFF_SCO     (OFF_RINV + 128)         // 79488
#define SMEM_BYTES  (OFF_SCO + M_TILE*SSTR*2)// 211072

__device__ __forceinline__ unsigned pk2f(float a, float b) {
    __half2 h = __floats2half2_rn(a, b);
    return *(unsigned*)&h;
}
__device__ __forceinline__ unsigned pk2h(__half a, __half b) {
    __half2 h = __halves2half2(a, b);
    return *(unsigned*)&h;
}

__device__ __forceinline__ void ldsm_x4(unsigned &r0, unsigned &r1, unsigned &r2,
                                        unsigned &r3, unsigned addr) {
    asm volatile("ldmatrix.sync.aligned.m8n8.x4.shared.b16 {%0,%1,%2,%3}, [%4];"
                 : "=r"(r0), "=r"(r1), "=r"(r2), "=r"(r3) : "r"(addr));
}
__device__ __forceinline__ void ldsm_x4_t(unsigned &r0, unsigned &r1, unsigned &r2,
                                          unsigned &r3, unsigned addr) {
    asm volatile("ldmatrix.sync.aligned.m8n8.x4.trans.shared.b16 {%0,%1,%2,%3}, [%4];"
                 : "=r"(r0), "=r"(r1), "=r"(r2), "=r"(r3) : "r"(addr));
}
__device__ __forceinline__ void mma_f16(float &d0, float &d1, float &d2, float &d3,
                                        unsigned a0, unsigned a1, unsigned a2, unsigned a3,
                                        unsigned b0, unsigned b1) {
    asm volatile("mma.sync.aligned.m16n8k16.row.col.f32.f16.f16.f32 "
                 "{%0,%1,%2,%3},{%4,%5,%6,%7},{%8,%9},{%0,%1,%2,%3};"
                 : "+f"(d0), "+f"(d1), "+f"(d2), "+f"(d3)
                 : "r"(a0), "r"(a1), "r"(a2), "r"(a3), "r"(b0), "r"(b1));
}

// convert 4 float4 regs -> fp16 tile rows in smem (128 rows x 64, stride KVSTR)
__device__ __forceinline__ void store_tile_h(__half* dst, const float4* kr, int t) {
    #pragma unroll
    for (int i = 0; i < 4; i++) {
        int idx = t + i * THREADS;
        int row = idx >> 4, c4 = idx & 15;
        float4 f = kr[i];
        *(uint2*)&dst[row * KVSTR + c4 * 4] =
            make_uint2(pk2f(f.x, f.y), pk2f(f.z, f.w));
    }
}
// V: hi/lo split so P@V stays ~fp32-exact in V
__device__ __forceinline__ void store_tile_hl(__half* hdst, __half* ldst,
                                              const float4* vr, int t) {
    #pragma unroll
    for (int i = 0; i < 4; i++) {
        int idx = t + i * THREADS;
        int row = idx >> 4, c4 = idx & 15;
        float4 f = vr[i];
        __half hx = __float2half_rn(f.x), hy = __float2half_rn(f.y);
        __half hz = __float2half_rn(f.z), hw = __float2half_rn(f.w);
        __half lx = __float2half_rn(f.x - __half2float(hx));
        __half ly = __float2half_rn(f.y - __half2float(hy));
        __half lz = __float2half_rn(f.z - __half2float(hz));
        __half lw = __float2half_rn(f.w - __half2float(hw));
        *(uint2*)&hdst[row * KVSTR + c4 * 4] = make_uint2(pk2h(hx, hy), pk2h(hz, hw));
        *(uint2*)&ldst[row * KVSTR + c4 * 4] = make_uint2(pk2h(lx, ly), pk2h(lz, lw));
    }
}

__global__ __launch_bounds__(THREADS, 1)
void sdpa_kernel(const float* __restrict__ q,
                 const float* __restrict__ k,
                 const float* __restrict__ v,
                 const int*   __restrict__ mask,
                 float* __restrict__ out,
                 float* __restrict__ attn)
{
    extern __shared__ char smc[];
    __half* kvb  = (__half*)smc;                 // 4 staging buffers
    __half* qh   = (__half*)(smc + OFF_QH);
    float*  red  = (float*)(smc + OFF_RED);
    float*  rinv = (float*)(smc + OFF_RINV);
    __half* sco  = (__half*)(smc + OFF_SCO);     // P (unnormalized exp), fp16
    const unsigned sbase = (unsigned)__cvta_generic_to_shared(smc);

    const int t    = threadIdx.x;
    const int lane = t & 31;
    const int w    = t >> 5;          // 0..15
    const int mblk = w & 1;           // 16-row block of M
    const int ng   = w >> 1;          // 0..7 n-group
    const int m0   = blockIdx.x * M_TILE;
    const int h    = blockIdx.y;
    const int b    = blockIdx.z;
    const int bh   = b * HEADS + h;

    const float4* qg4 = (const float4*)(q + ((size_t)bh * T_SEQ + m0) * CDIM);
    const float4* kg4 = (const float4*)(k + (size_t)bh * T_SEQ * CDIM);
    const float4* vg4 = (const float4*)(v + (size_t)bh * T_SEQ * CDIM);
    const int*    mg  = mask + ((size_t)b * T_SEQ + m0) * T_SEQ;   // mask [B,1,T,T]
    float* attng = attn + ((size_t)bh * T_SEQ + m0) * T_SEQ;
    float* outg  = out  + ((size_t)bh * T_SEQ + m0) * CDIM;

    // ---- Q load (1 float4/thread), scale 1/8, fp16 store ----
    {
        int row = t >> 4, c4 = t & 15;
        float4 f = qg4[t];
        *(uint2*)&qh[row * KVSTR + c4 * 4] =
            make_uint2(pk2f(f.x * 0.125f, f.y * 0.125f), pk2f(f.z * 0.125f, f.w * 0.125f));
    }

    // ---- K prologue: tile0 -> buf0, tile1 -> regs ----
    float4 kreg[4];
    #pragma unroll
    for (int i = 0; i < 4; i++) kreg[i] = kg4[t + i * THREADS];
    store_tile_h(kvb, kreg, t);
    #pragma unroll
    for (int i = 0; i < 4; i++) kreg[i] = kg4[(KTILE * CDIM / 4) + t + i * THREADS];
    __syncthreads();   // qh + K buf0 visible

    // ---- Q A-fragments, held in registers all of Phase A ----
    unsigned qa[4][4];
    {
        int sub = lane >> 3, i = lane & 7;
        int row = mblk * 16 + (sub & 1) * 8 + i;
        int colb = (sub >> 1) * 8;
        #pragma unroll
        for (int ks = 0; ks < 4; ks++) {
            unsigned addr = sbase + OFF_QH + (unsigned)(row * KVSTR + ks * 16 + colb) * 2;
            ldsm_x4(qa[ks][0], qa[ks][1], qa[ks][2], qa[ks][3], addr);
        }
    }

    const int gq  = lane >> 2;         // 0..7
    const int t2  = (lane & 3) * 2;
    const int rowA = mblk * 16 + gq;   // local q row (and +8)
    const int iL = lane & 7, subL = lane >> 3;
    float rs0 = 0.f, rs1 = 0.f;

    // ================= Phase A: S = (Q/8)K^T via HMMA, fused mask/exp/rowsum =========
    #pragma unroll 1
    for (int r = 0; r < ROUNDS; r++) {
        __syncthreads();
        if (r + 1 < ROUNDS) store_tile_h(kvb + ((r + 1) & 1) * (KTILE * KVSTR), kreg, t);
        if (r + 2 < ROUNDS) {
            #pragma unroll
            for (int i = 0; i < 4; i++)
                kreg[i] = kg4[(size_t)(r + 2) * (KTILE * CDIM / 4) + t + i * THREADS];
        }
        const unsigned bufb = sbase + (r & 1) * KVBUF_BYTES;
        const int j0w = ng * 16;
        #pragma unroll
        for (int nt = 0; nt < 2; nt++) {
            const int j0 = r * KTILE + j0w + nt * 8;
            int2 mlo = *(const int2*)&mg[(size_t)rowA * T_SEQ + j0 + t2];
            int2 mhi = *(const int2*)&mg[(size_t)(rowA + 8) * T_SEQ + j0 + t2];
            float d0 = 0.f, d1 = 0.f, d2 = 0.f, d3 = 0.f;
            #pragma unroll
            for (int s = 0; s < 2; s++) {
                unsigned b0, b1, b2, b3;
                unsigned addr = bufb +
                    (unsigned)((j0w + nt * 8 + iL) * KVSTR + s * 32 + subL * 8) * 2;
                ldsm_x4(b0, b1, b2, b3, addr);
                mma_f16(d0, d1, d2, d3, qa[2*s][0], qa[2*s][1], qa[2*s][2], qa[2*s][3], b0, b1);
                mma_f16(d0, d1, d2, d3, qa[2*s+1][0], qa[2*s+1][1], qa[2*s+1][2], qa[2*s+1][3], b2, b3);
            }
            float e0 = mlo.x ? __expf(d0) : 0.f;
            float e1 = mlo.y ? __expf(d1) : 0.f;
            float e2 = mhi.x ? __expf(d2) : 0.f;
            float e3 = mhi.y ? __expf(d3) : 0.f;
            *(__half2*)&sco[rowA * SSTR + j0 + t2]       = __floats2half2_rn(e0, e1);
            *(__half2*)&sco[(rowA + 8) * SSTR + j0 + t2] = __floats2half2_rn(e2, e3);
            rs0 += e0 + e1;
            rs1 += e2 + e3;
        }
    }

    // warp-local rowsum reduce over the 4 lanes sharing a row
    rs0 += __shfl_xor_sync(0xffffffffu, rs0, 1);
    rs0 += __shfl_xor_sync(0xffffffffu, rs0, 2);
    rs1 += __shfl_xor_sync(0xffffffffu, rs1, 1);
    rs1 += __shfl_xor_sync(0xffffffffu, rs1, 2);

    // ---- V prologue (buf0 free after last round's entry sync) + red stores ----
    float4 vreg[4];
    #pragma unroll
    for (int i = 0; i < 4; i++) vreg[i] = vg4[t + i * THREADS];
    if ((lane & 3) == 0) {
        red[ng * 32 + rowA]     = rs0;
        red[ng * 32 + rowA + 8] = rs1;
    }
    store_tile_hl(kvb, kvb + 2 * (KTILE * KVSTR), vreg, t);   // tile0 -> vh buf0 / vl buf2
    #pragma unroll
    for (int i = 0; i < 4; i++) vreg[i] = vg4[(KTILE * CDIM / 4) + t + i * THREADS];
    __syncthreads();
    if (t < 32) {
        float s = 0.f;
        #pragma unroll
        for (int g8 = 0; g8 < 8; g8++) s += red[g8 * 32 + t];
        rinv[t] = 1.0f / s;
    }

    // ================= Phase B: out = P @ (Vh + Vl), attn write interleaved =========
    float ah0=0,ah1=0,ah2=0,ah3=0, al0=0,al1=0,al2=0,al3=0;
    const int c0  = ng * 8;
    const int m0l = mblk * 16;
    const unsigned aBase = sbase + OFF_SCO +
        (unsigned)((m0l + ((lane >> 3) & 1) * 8 + (lane & 7)) * SSTR + ((lane >> 4) & 1) * 8) * 2;
    const unsigned vLane = (unsigned)(((lane >> 3) * 8 + (lane & 7)) * KVSTR + c0) * 2;

    #pragma unroll 1
    for (int r = 0; r < ROUNDS; r++) {
        __syncthreads();   // round 0: also publishes rinv + vh/vl buf0
        if (r + 1 < ROUNDS)
            store_tile_hl(kvb + ((r + 1) & 1) * (KTILE * KVSTR),
                          kvb + (2 + ((r + 1) & 1)) * (KTILE * KVSTR), vreg, t);
        if (r + 2 < ROUNDS) {
            #pragma unroll
            for (int i = 0; i < 4; i++)
                vreg[i] = vg4[(size_t)(r + 2) * (KTILE * CDIM / 4) + t + i * THREADS];
        }
        const unsigned vhB = sbase + (r & 1) * KVBUF_BYTES + vLane;
        const unsigned vlB = sbase + (2 + (r & 1)) * KVBUF_BYTES + vLane;
        const int k0r = r * KTILE;
        #pragma unroll
        for (int sp = 0; sp < 4; sp++) {
            unsigned vh0, vh1, vh2, vh3, vl0, vl1, vl2, vl3;
            ldsm_x4_t(vh0, vh1, vh2, vh3, vhB + (unsigned)(sp * 32 * KVSTR) * 2);
            ldsm_x4_t(vl0, vl1, vl2, vl3, vlB + (unsigned)(sp * 32 * KVSTR) * 2);
            unsigned a0, a1, a2, a3;
            ldsm_x4(a0, a1, a2, a3, aBase + (unsigned)(k0r + sp * 32) * 2);
            mma_f16(ah0, ah1, ah2, ah3, a0, a1, a2, a3, vh0, vh1);
            mma_f16(al0, al1, al2, al3, a0, a1, a2, a3, vl0, vl1);
            ldsm_x4(a0, a1, a2, a3, aBase + (unsigned)(k0r + sp * 32 + 16) * 2);
            mma_f16(ah0, ah1, ah2, ah3, a0, a1, a2, a3, vh2, vh3);
            mma_f16(al0, al1, al2, al3, a0, a1, a2, a3, vl2, vl3);
        }
        // interleaved normalized-attn write (2 of 32 chunks per round)
        #pragma unroll
        for (int ii = 0; ii < 2; ii++) {
            int idx = (r * 2 + ii) * THREADS + t;
            int rr = idx >> 9, cc = idx & 511;
            __half2 p0 = *(__half2*)&sco[rr * SSTR + cc * 4];
            __half2 p1 = *(__half2*)&sco[rr * SSTR + cc * 4 + 2];
            float ri = rinv[rr];
            float2 f0 = __half22float2(p0), f1 = __half22float2(p1);
            ((float4*)attng)[(size_t)rr * 512 + cc] =
                make_float4(f0.x * ri, f0.y * ri, f1.x * ri, f1.y * ri);
        }
    }

    // ---- epilogue: out = (acc_hi + acc_lo) * rinv ----
    {
        float ri0 = rinv[m0l + gq], ri1 = rinv[m0l + gq + 8];
        *(float2*)&outg[(m0l + gq) * CDIM + c0 + t2] =
            make_float2((ah0 + al0) * ri0, (ah1 + al1) * ri0);
        *(float2*)&outg[(m0l + gq + 8) * CDIM + c0 + t2] =
            make_float2((ah2 + al2) * ri1, (ah3 + al3) * ri1);
    }
}

extern "C" void kernel_launch(void* const* d_in, const int* in_sizes, int n_in,
                              void* d_out, int out_size)
{
    const float* q    = (const float*)d_in[0];
    const float* k    = (const float*)d_in[1];
    const float* v    = (const float*)d_in[2];
    const int*   mask = (const int*)d_in[3];

    float* out  = (float*)d_out;                                   // [B,H,T,C]
    float* attn = out + (size_t)BATCH * HEADS * T_SEQ * CDIM;      // [B,H,T,T]

    cudaFuncSetAttribute(sdpa_kernel,
                         cudaFuncAttributeMaxDynamicSharedMemorySize, SMEM_BYTES);

    dim3 grid(T_SEQ / M_TILE, HEADS, BATCH);   // (64, 16, 2)
    sdpa_kernel<<<grid, THREADS, SMEM_BYTES>>>(q, k, v, mask, out, attn);
}

// round 7
// speedup vs baseline: 2.4310x; 1.1373x over previous
#include <cuda_runtime.h>
#include <cuda_fp16.h>
#include <cstddef>

// Problem: B=2, H=16, T=2048, C=64
#define T_SEQ   2048
#define CDIM    64
#define HEADS   16
#define BATCH   2
#define M_TILE  32
#define KTILE   128
#define ROUNDS  (T_SEQ/KTILE)    // 16
#define THREADS 512
#define KVSTR   72               // halves per staged K/V row (pad)
#define SSTR    2056             // halves per scores row (pad)
#define PSTR    68               // floats per partial-out row (pad)

#define KVBUF_BYTES (KTILE*KVSTR*2)            // 18432
#define OFF_QH      (4*KVBUF_BYTES)            // 73728
#define OFF_RED     (OFF_QH + M_TILE*KVSTR*2)  // 78336
#define OFF_RINV    (OFF_RED + 16*32*4)        // 80384
#define OFF_SCO     (OFF_RINV + 128)           // 80512
#define SMEM_BYTES  (OFF_SCO + M_TILE*SSTR*2)  // 212096

__device__ __forceinline__ unsigned pk2f(float a, float b) {
    __half2 h = __floats2half2_rn(a, b);
    return *(unsigned*)&h;
}
__device__ __forceinline__ unsigned pk2h(__half a, __half b) {
    __half2 h = __halves2half2(a, b);
    return *(unsigned*)&h;
}
__device__ __forceinline__ void ldsm_x4(unsigned &r0, unsigned &r1, unsigned &r2,
                                        unsigned &r3, unsigned addr) {
    asm volatile("ldmatrix.sync.aligned.m8n8.x4.shared.b16 {%0,%1,%2,%3}, [%4];"
                 : "=r"(r0), "=r"(r1), "=r"(r2), "=r"(r3) : "r"(addr));
}
__device__ __forceinline__ void ldsm_x4_t(unsigned &r0, unsigned &r1, unsigned &r2,
                                          unsigned &r3, unsigned addr) {
    asm volatile("ldmatrix.sync.aligned.m8n8.x4.trans.shared.b16 {%0,%1,%2,%3}, [%4];"
                 : "=r"(r0), "=r"(r1), "=r"(r2), "=r"(r3) : "r"(addr));
}
__device__ __forceinline__ void mma_f16(float &d0, float &d1, float &d2, float &d3,
                                        unsigned a0, unsigned a1, unsigned a2, unsigned a3,
                                        unsigned b0, unsigned b1) {
    asm volatile("mma.sync.aligned.m16n8k16.row.col.f32.f16.f16.f32 "
                 "{%0,%1,%2,%3},{%4,%5,%6,%7},{%8,%9},{%0,%1,%2,%3};"
                 : "+f"(d0), "+f"(d1), "+f"(d2), "+f"(d3)
                 : "r"(a0), "r"(a1), "r"(a2), "r"(a3), "r"(b0), "r"(b1));
}

__device__ __forceinline__ void store_tile_h(__half* dst, const float4* kr, int t) {
    #pragma unroll
    for (int i = 0; i < 4; i++) {
        int idx = t + i * THREADS;
        int row = idx >> 4, c4 = idx & 15;
        float4 f = kr[i];
        *(uint2*)&dst[row * KVSTR + c4 * 4] = make_uint2(pk2f(f.x, f.y), pk2f(f.z, f.w));
    }
}
__device__ __forceinline__ void store_tile_hl(__half* hdst, __half* ldst,
                                              const float4* vr, int t) {
    #pragma unroll
    for (int i = 0; i < 4; i++) {
        int idx = t + i * THREADS;
        int row = idx >> 4, c4 = idx & 15;
        float4 f = vr[i];
        __half hx = __float2half_rn(f.x), hy = __float2half_rn(f.y);
        __half hz = __float2half_rn(f.z), hw = __float2half_rn(f.w);
        __half lx = __float2half_rn(f.x - __half2float(hx));
        __half ly = __float2half_rn(f.y - __half2float(hy));
        __half lz = __float2half_rn(f.z - __half2float(hz));
        __half lw = __float2half_rn(f.w - __half2float(hw));
        *(uint2*)&hdst[row * KVSTR + c4 * 4] = make_uint2(pk2h(hx, hy), pk2h(hz, hw));
        *(uint2*)&ldst[row * KVSTR + c4 * 4] = make_uint2(pk2h(lx, ly), pk2h(lz, lw));
    }
}

__global__ __launch_bounds__(THREADS, 1)
void sdpa_kernel(const float* __restrict__ q,
                 const float* __restrict__ k,
                 const float* __restrict__ v,
                 const int*   __restrict__ mask,
                 float* __restrict__ out,
                 float* __restrict__ attn)
{
    extern __shared__ char smc[];
    __half* kvb  = (__half*)smc;
    __half* qh   = (__half*)(smc + OFF_QH);
    float*  red  = (float*)(smc + OFF_RED);
    float*  rinv = (float*)(smc + OFF_RINV);
    __half* sco  = (__half*)(smc + OFF_SCO);
    const unsigned sbase = (unsigned)__cvta_generic_to_shared(smc);

    const int t    = threadIdx.x;
    const int lane = t & 31;
    const int w    = t >> 5;
    const int m0   = blockIdx.x * M_TILE;
    const int h    = blockIdx.y;
    const int b    = blockIdx.z;
    const int bh   = b * HEADS + h;

    const float4* qg4 = (const float4*)(q + ((size_t)bh * T_SEQ + m0) * CDIM);
    const float4* kg4 = (const float4*)(k + (size_t)bh * T_SEQ * CDIM);
    const float4* vg4 = (const float4*)(v + (size_t)bh * T_SEQ * CDIM);
    const int*    mg  = mask + ((size_t)b * T_SEQ + m0) * T_SEQ;
    float* attng = attn + ((size_t)bh * T_SEQ + m0) * T_SEQ;
    float* outg  = out  + ((size_t)bh * T_SEQ + m0) * CDIM;

    // ---- Q load (scaled 1/8) -> fp16 smem ----
    {
        int row = t >> 4, c4 = t & 15;
        float4 f = qg4[t];
        *(uint2*)&qh[row * KVSTR + c4 * 4] =
            make_uint2(pk2f(f.x * 0.125f, f.y * 0.125f), pk2f(f.z * 0.125f, f.w * 0.125f));
    }

    // ---- K prologue: tile0 -> buf0, tile1 -> regs ----
    float4 kreg[4];
    #pragma unroll
    for (int i = 0; i < 4; i++) kreg[i] = kg4[t + i * THREADS];
    store_tile_h(kvb, kreg, t);
    #pragma unroll
    for (int i = 0; i < 4; i++) kreg[i] = kg4[(KTILE * CDIM / 4) + t + i * THREADS];
    __syncthreads();   // qh + K buf0 visible

    // ---- Q A-fragments (both 16-row blocks) held in regs all Phase A ----
    unsigned qa[2][4][4];
    {
        int rsel = lane & 15, csel = (lane >> 4) & 1;
        #pragma unroll
        for (int mb = 0; mb < 2; mb++)
            #pragma unroll
            for (int ks = 0; ks < 4; ks++) {
                unsigned addr = sbase + OFF_QH +
                    (unsigned)((mb * 16 + rsel) * KVSTR + ks * 16 + csel * 8) * 2;
                ldsm_x4(qa[mb][ks][0], qa[mb][ks][1], qa[mb][ks][2], qa[mb][ks][3], addr);
            }
    }

    const int iL = lane & 7, subL = lane >> 3;
    const int gq = lane >> 2, t2 = (lane & 3) * 2;
    const int jw = w * 8;            // warp's 8-col slice within each round
    float rsum[4] = {0.f, 0.f, 0.f, 0.f};

    // mask prefetch for round 0
    int2 mpre[4];
    #pragma unroll
    for (int u = 0; u < 4; u++)
        mpre[u] = *(const int2*)&mg[(size_t)(gq + 8 * u) * T_SEQ + jw + t2];

    // ================ Phase A: S = (Q/8)K^T, warp = 8 cols x 32 rows ================
    #pragma unroll 1
    for (int r = 0; r < ROUNDS; r++) {
        __syncthreads();
        if (r + 1 < ROUNDS) store_tile_h(kvb + ((r + 1) & 1) * (KTILE * KVSTR), kreg, t);
        if (r + 2 < ROUNDS) {
            #pragma unroll
            for (int i = 0; i < 4; i++)
                kreg[i] = kg4[(size_t)(r + 2) * (KTILE * CDIM / 4) + t + i * THREADS];
        }
        int2 mcur[4];
        #pragma unroll
        for (int u = 0; u < 4; u++) mcur[u] = mpre[u];
        if (r + 1 < ROUNDS) {
            #pragma unroll
            for (int u = 0; u < 4; u++)
                mpre[u] = *(const int2*)&mg[(size_t)(gq + 8 * u) * T_SEQ +
                                            (r + 1) * KTILE + jw + t2];
        }

        const unsigned bufb = sbase + (r & 1) * KVBUF_BYTES;
        unsigned bb[2][4];
        #pragma unroll
        for (int s = 0; s < 2; s++) {
            unsigned addr = bufb + (unsigned)((jw + iL) * KVSTR + s * 32 + subL * 8) * 2;
            ldsm_x4(bb[s][0], bb[s][1], bb[s][2], bb[s][3], addr);
        }

        float d[2][4] = {{0.f,0.f,0.f,0.f},{0.f,0.f,0.f,0.f}};
        #pragma unroll
        for (int mb = 0; mb < 2; mb++) {
            mma_f16(d[mb][0], d[mb][1], d[mb][2], d[mb][3],
                    qa[mb][0][0], qa[mb][0][1], qa[mb][0][2], qa[mb][0][3], bb[0][0], bb[0][1]);
            mma_f16(d[mb][0], d[mb][1], d[mb][2], d[mb][3],
                    qa[mb][1][0], qa[mb][1][1], qa[mb][1][2], qa[mb][1][3], bb[0][2], bb[0][3]);
            mma_f16(d[mb][0], d[mb][1], d[mb][2], d[mb][3],
                    qa[mb][2][0], qa[mb][2][1], qa[mb][2][2], qa[mb][2][3], bb[1][0], bb[1][1]);
            mma_f16(d[mb][0], d[mb][1], d[mb][2], d[mb][3],
                    qa[mb][3][0], qa[mb][3][1], qa[mb][3][2], qa[mb][3][3], bb[1][2], bb[1][3]);
        }

        const int j = r * KTILE + jw + t2;
        #pragma unroll
        for (int mb = 0; mb < 2; mb++)
            #pragma unroll
            for (int hi = 0; hi < 2; hi++) {
                int u = mb * 2 + hi;
                float e0 = mcur[u].x ? __expf(d[mb][hi*2])   : 0.f;
                float e1 = mcur[u].y ? __expf(d[mb][hi*2+1]) : 0.f;
                int row = mb * 16 + gq + hi * 8;
                *(__half2*)&sco[row * SSTR + j] = __floats2half2_rn(e0, e1);
                rsum[u] += e0 + e1;
            }
    }

    // rowsum: reduce over 4 lanes sharing a row, stash per-warp partials
    #pragma unroll
    for (int u = 0; u < 4; u++) {
        rsum[u] += __shfl_xor_sync(0xffffffffu, rsum[u], 1);
        rsum[u] += __shfl_xor_sync(0xffffffffu, rsum[u], 2);
    }
    if ((lane & 3) == 0) {
        #pragma unroll
        for (int u = 0; u < 4; u++) red[w * 32 + gq + 8 * u] = rsum[u];
    }

    // ---- V prologue: tile0 -> vh buf0 / vl buf2, tile1 -> regs ----
    float4 vreg[4];
    #pragma unroll
    for (int i = 0; i < 4; i++) vreg[i] = vg4[t + i * THREADS];
    store_tile_hl(kvb, kvb + 2 * (KTILE * KVSTR), vreg, t);
    #pragma unroll
    for (int i = 0; i < 4; i++) vreg[i] = vg4[(KTILE * CDIM / 4) + t + i * THREADS];
    __syncthreads();
    if (t < 32) {
        float s = 0.f;
        #pragma unroll
        for (int g = 0; g < 16; g++) s += red[g * 32 + t];
        rinv[t] = 1.0f / s;
    }

    // ================ Phase B: split-K, warp = (n-half, j-chunk16) ================
    const int ng2 = w & 1;
    const int kg  = w >> 1;          // 0..7: j-chunk of 16 within each round
    const int c0  = ng2 * 32;
    const unsigned vLane = (unsigned)((kg * 16 + (lane & 15)) * KVSTR + c0 +
                                      ((lane >> 4) & 1) * 8) * 2;
    const unsigned aLane = sbase + OFF_SCO +
        (unsigned)((lane & 15) * SSTR + ((lane >> 4) & 1) * 8) * 2;

    float accH[2][4][4], accL[2][4][4];
    #pragma unroll
    for (int mb = 0; mb < 2; mb++)
        #pragma unroll
        for (int nn = 0; nn < 4; nn++)
            #pragma unroll
            for (int d = 0; d < 4; d++) { accH[mb][nn][d] = 0.f; accL[mb][nn][d] = 0.f; }

    #pragma unroll 1
    for (int r = 0; r < ROUNDS; r++) {
        __syncthreads();   // r==0: also publishes rinv + vh/vl buf0
        if (r + 1 < ROUNDS)
            store_tile_hl(kvb + ((r + 1) & 1) * (KTILE * KVSTR),
                          kvb + (2 + ((r + 1) & 1)) * (KTILE * KVSTR), vreg, t);
        if (r + 2 < ROUNDS) {
            #pragma unroll
            for (int i = 0; i < 4; i++)
                vreg[i] = vg4[(size_t)(r + 2) * (KTILE * CDIM / 4) + t + i * THREADS];
        }

        const int j0 = r * KTILE + kg * 16;
        unsigned a0[2][4];
        #pragma unroll
        for (int mb = 0; mb < 2; mb++)
            ldsm_x4(a0[mb][0], a0[mb][1], a0[mb][2], a0[mb][3],
                    aLane + (unsigned)(mb * 16 * SSTR + j0) * 2);

        unsigned vh[2][4], vl[2][4];
        #pragma unroll
        for (int cc = 0; cc < 2; cc++) {
            ldsm_x4_t(vh[cc][0], vh[cc][1], vh[cc][2], vh[cc][3],
                      sbase + (r & 1) * KVBUF_BYTES + vLane + cc * 32);
            ldsm_x4_t(vl[cc][0], vl[cc][1], vl[cc][2], vl[cc][3],
                      sbase + (2 + (r & 1)) * KVBUF_BYTES + vLane + cc * 32);
        }

        #pragma unroll
        for (int mb = 0; mb < 2; mb++)
            #pragma unroll
            for (int nn = 0; nn < 4; nn++) {
                unsigned bh0 = vh[nn >> 1][(nn & 1) * 2], bh1 = vh[nn >> 1][(nn & 1) * 2 + 1];
                unsigned bl0 = vl[nn >> 1][(nn & 1) * 2], bl1 = vl[nn >> 1][(nn & 1) * 2 + 1];
                mma_f16(accH[mb][nn][0], accH[mb][nn][1], accH[mb][nn][2], accH[mb][nn][3],
                        a0[mb][0], a0[mb][1], a0[mb][2], a0[mb][3], bh0, bh1);
                mma_f16(accL[mb][nn][0], accL[mb][nn][1], accL[mb][nn][2], accL[mb][nn][3],
                        a0[mb][0], a0[mb][1], a0[mb][2], a0[mb][3], bl0, bl1);
            }

        // interleaved normalized-attn write (2 of 32 chunks per round)
        #pragma unroll
        for (int ii = 0; ii < 2; ii++) {
            int idx = (r * 2 + ii) * THREADS + t;
            int rr = idx >> 9, cc = idx & 511;
            __half2 p0 = *(__half2*)&sco[rr * SSTR + cc * 4];
            __half2 p1 = *(__half2*)&sco[rr * SSTR + cc * 4 + 2];
            float ri = rinv[rr];
            float2 f0 = __half22float2(p0), f1 = __half22float2(p1);
            ((float4*)attng)[(size_t)rr * 512 + cc] =
                make_float4(f0.x * ri, f0.y * ri, f1.x * ri, f1.y * ri);
        }
    }

    // ---- cross-kg reduction (reuse sco region; attn fully written) ----
    __syncthreads();
    float* part = (float*)(smc + OFF_SCO);   // [8 kg][32 rows][PSTR]
    #pragma unroll
    for (int mb = 0; mb < 2; mb++)
        #pragma unroll
        for (int nn = 0; nn < 4; nn++) {
            int row = mb * 16 + gq;
            int col = c0 + nn * 8 + t2;
            *(float2*)&part[kg * (32 * PSTR) + row * PSTR + col] =
                make_float2(accH[mb][nn][0] + accL[mb][nn][0],
                            accH[mb][nn][1] + accL[mb][nn][1]);
            *(float2*)&part[kg * (32 * PSTR) + (row + 8) * PSTR + col] =
                make_float2(accH[mb][nn][2] + accL[mb][nn][2],
                            accH[mb][nn][3] + accL[mb][nn][3]);
        }
    __syncthreads();

    // 32 rows x 16 c4 = 512 float4: one per thread
    {
        int row = t >> 4, c4 = t & 15;
        float4 s = {0.f, 0.f, 0.f, 0.f};
        #pragma unroll
        for (int g = 0; g < 8; g++) {
            float4 p = *(float4*)&part[g * (32 * PSTR) + row * PSTR + c4 * 4];
            s.x += p.x; s.y += p.y; s.z += p.z; s.w += p.w;
        }
        float ri = rinv[row];
        s.x *= ri; s.y *= ri; s.z *= ri; s.w *= ri;
        ((float4*)outg)[row * 16 + c4] = s;
    }
}

extern "C" void kernel_launch(void* const* d_in, const int* in_sizes, int n_in,
                              void* d_out, int out_size)
{
    const float* q    = (const float*)d_in[0];
    const float* k    = (const float*)d_in[1];
    const float* v    = (const float*)d_in[2];
    const int*   mask = (const int*)d_in[3];

    float* out  = (float*)d_out;                                   // [B,H,T,C]
    float* attn = out + (size_t)BATCH * HEADS * T_SEQ * CDIM;      // [B,H,T,T]

    cudaFuncSetAttribute(sdpa_kernel,
                         cudaFuncAttributeMaxDynamicSharedMemorySize, SMEM_BYTES);

    dim3 grid(T_SEQ / M_TILE, HEADS, BATCH);   // (64, 16, 2)
    sdpa_kernel<<<grid, THREADS, SMEM_BYTES>>>(q, k, v, mask, out, attn);
}

// round 8
// speedup vs baseline: 2.8055x; 1.1541x over previous
#include <cuda_runtime.h>
#include <cuda_fp16.h>
#include <cstddef>

// Problem: B=2, H=16, T=2048, C=64
#define T_SEQ   2048
#define CDIM    64
#define HEADS   16
#define BATCH   2
#define M_TILE  32
#define KTILE   128
#define ROUNDS  (T_SEQ/KTILE)    // 16
#define THREADS 512
#define KVSTR   72               // halves per staged K/V row (pad)
#define SSTR    2056             // halves per scores row (pad)
#define PSTR    68               // floats per partial-out row (pad)

#define KVBUF_BYTES (KTILE*KVSTR*2)            // 18432
#define OFF_V       (2*KVBUF_BYTES)            // 36864
#define OFF_QH      (4*KVBUF_BYTES)            // 73728
#define OFF_RED     (OFF_QH + M_TILE*KVSTR*2)  // 78336
#define OFF_RINV    (OFF_RED + 16*16*4)        // 79360
#define OFF_SCO     (OFF_RINV + 128)           // 79488
#define SMEM_BYTES  (OFF_SCO + M_TILE*SSTR*2)  // 211072

__device__ __forceinline__ unsigned pk2f(float a, float b) {
    __half2 h = __floats2half2_rn(a, b);
    return *(unsigned*)&h;
}
__device__ __forceinline__ void ldsm_x4(unsigned &r0, unsigned &r1, unsigned &r2,
                                        unsigned &r3, unsigned addr) {
    asm volatile("ldmatrix.sync.aligned.m8n8.x4.shared.b16 {%0,%1,%2,%3}, [%4];"
                 : "=r"(r0), "=r"(r1), "=r"(r2), "=r"(r3) : "r"(addr));
}
__device__ __forceinline__ void ldsm_x4_t(unsigned &r0, unsigned &r1, unsigned &r2,
                                          unsigned &r3, unsigned addr) {
    asm volatile("ldmatrix.sync.aligned.m8n8.x4.trans.shared.b16 {%0,%1,%2,%3}, [%4];"
                 : "=r"(r0), "=r"(r1), "=r"(r2), "=r"(r3) : "r"(addr));
}
__device__ __forceinline__ void mma_f16(float &d0, float &d1, float &d2, float &d3,
                                        unsigned a0, unsigned a1, unsigned a2, unsigned a3,
                                        unsigned b0, unsigned b1) {
    asm volatile("mma.sync.aligned.m16n8k16.row.col.f32.f16.f16.f32 "
                 "{%0,%1,%2,%3},{%4,%5,%6,%7},{%8,%9},{%0,%1,%2,%3};"
                 : "+f"(d0), "+f"(d1), "+f"(d2), "+f"(d3)
                 : "r"(a0), "r"(a1), "r"(a2), "r"(a3), "r"(b0), "r"(b1));
}
__device__ __forceinline__ void store_tile_h(__half* dst, const float4* kr, int t) {
    #pragma unroll
    for (int i = 0; i < 4; i++) {
        int idx = t + i * THREADS;
        int row = idx >> 4, c4 = idx & 15;
        float4 f = kr[i];
        *(uint2*)&dst[row * KVSTR + c4 * 4] = make_uint2(pk2f(f.x, f.y), pk2f(f.z, f.w));
    }
}

__global__ __launch_bounds__(THREADS, 1)
void sdpa_kernel(const float* __restrict__ q,
                 const float* __restrict__ k,
                 const float* __restrict__ v,
                 const int*   __restrict__ mask,
                 float* __restrict__ out,
                 float* __restrict__ attn)
{
    extern __shared__ char smc[];
    __half* kvbK = (__half*)smc;
    __half* kvbV = (__half*)(smc + OFF_V);
    __half* qh   = (__half*)(smc + OFF_QH);
    float*  red  = (float*)(smc + OFF_RED);
    float*  rinv = (float*)(smc + OFF_RINV);
    __half* sco  = (__half*)(smc + OFF_SCO);
    const unsigned sbase = (unsigned)__cvta_generic_to_shared(smc);

    const int t    = threadIdx.x;
    const int lane = t & 31;
    const int w    = t >> 5;
    const int mb   = w & 1;           // 16-row block
    const int jg   = w >> 1;          // 0..7: 16-col j slice per round
    const int m0   = blockIdx.x * M_TILE;
    const int h    = blockIdx.y;
    const int b    = blockIdx.z;
    const int bh   = b * HEADS + h;

    const float4* qg4 = (const float4*)(q + ((size_t)bh * T_SEQ + m0) * CDIM);
    const float4* kg4 = (const float4*)(k + (size_t)bh * T_SEQ * CDIM);
    const float4* vg4 = (const float4*)(v + (size_t)bh * T_SEQ * CDIM);
    const int*    mg  = mask + ((size_t)b * T_SEQ + m0) * T_SEQ;
    float* attng = attn + ((size_t)bh * T_SEQ + m0) * T_SEQ;
    float* outg  = out  + ((size_t)bh * T_SEQ + m0) * CDIM;

    // ---- Q load (scaled 1/8) -> fp16 smem ----
    {
        int row = t >> 4, c4 = t & 15;
        float4 f = qg4[t];
        *(uint2*)&qh[row * KVSTR + c4 * 4] =
            make_uint2(pk2f(f.x * 0.125f, f.y * 0.125f), pk2f(f.z * 0.125f, f.w * 0.125f));
    }

    // ---- prologue: tile0 -> smem bufs, tile1 -> regs ----
    float4 kreg[4], vreg[4];
    #pragma unroll
    for (int i = 0; i < 4; i++) kreg[i] = kg4[t + i * THREADS];
    #pragma unroll
    for (int i = 0; i < 4; i++) vreg[i] = vg4[t + i * THREADS];
    store_tile_h(kvbK, kreg, t);
    store_tile_h(kvbV, vreg, t);
    #pragma unroll
    for (int i = 0; i < 4; i++) kreg[i] = kg4[(KTILE * CDIM / 4) + t + i * THREADS];
    #pragma unroll
    for (int i = 0; i < 4; i++) vreg[i] = vg4[(KTILE * CDIM / 4) + t + i * THREADS];
    __syncthreads();   // qh + bufs 0 visible

    // ---- Q A-fragments for this warp's 16-row block (held all kernel) ----
    unsigned qa[4][4];
    {
        int rsel = lane & 15, csel = (lane >> 4) & 1;
        #pragma unroll
        for (int ks = 0; ks < 4; ks++) {
            unsigned addr = sbase + OFF_QH +
                (unsigned)((mb * 16 + rsel) * KVSTR + ks * 16 + csel * 8) * 2;
            ldsm_x4(qa[ks][0], qa[ks][1], qa[ks][2], qa[ks][3], addr);
        }
    }

    const int iL = lane & 7, subL = lane >> 3;
    const int gq = lane >> 2, t2 = (lane & 3) * 2;
    const int rowA = mb * 16 + gq;
    float rs0 = 0.f, rs1 = 0.f;
    float acc[8][4];
    #pragma unroll
    for (int nn = 0; nn < 8; nn++)
        #pragma unroll
        for (int d = 0; d < 4; d++) acc[nn][d] = 0.f;

    // ================= fused round loop =================
    #pragma unroll 1
    for (int r = 0; r < ROUNDS; r++) {
        __syncthreads();
        if (r + 1 < ROUNDS) {
            store_tile_h(kvbK + ((r + 1) & 1) * (KTILE * KVSTR), kreg, t);
            store_tile_h(kvbV + ((r + 1) & 1) * (KTILE * KVSTR), vreg, t);
        }
        if (r + 2 < ROUNDS) {
            #pragma unroll
            for (int i = 0; i < 4; i++)
                kreg[i] = kg4[(size_t)(r + 2) * (KTILE * CDIM / 4) + t + i * THREADS];
            #pragma unroll
            for (int i = 0; i < 4; i++)
                vreg[i] = vg4[(size_t)(r + 2) * (KTILE * CDIM / 4) + t + i * THREADS];
        }

        const int jbase = r * KTILE + jg * 16;
        // mask loads (early: latency hidden behind mma)
        int2 mc[4];
        #pragma unroll
        for (int r2 = 0; r2 < 2; r2++)
            #pragma unroll
            for (int nt = 0; nt < 2; nt++)
                mc[r2 * 2 + nt] =
                    *(const int2*)&mg[(size_t)(rowA + r2 * 8) * T_SEQ + jbase + nt * 8 + t2];

        // ---- S = (Q/8)K^T : warp's 16x16 tile ----
        const unsigned kb = sbase + (r & 1) * KVBUF_BYTES;
        float d[2][4] = {{0.f,0.f,0.f,0.f},{0.f,0.f,0.f,0.f}};
        #pragma unroll
        for (int nt = 0; nt < 2; nt++) {
            unsigned bb[2][4];
            #pragma unroll
            for (int s = 0; s < 2; s++) {
                unsigned addr = kb +
                    (unsigned)((jg * 16 + nt * 8 + iL) * KVSTR + s * 32 + subL * 8) * 2;
                ldsm_x4(bb[s][0], bb[s][1], bb[s][2], bb[s][3], addr);
            }
            mma_f16(d[nt][0], d[nt][1], d[nt][2], d[nt][3],
                    qa[0][0], qa[0][1], qa[0][2], qa[0][3], bb[0][0], bb[0][1]);
            mma_f16(d[nt][0], d[nt][1], d[nt][2], d[nt][3],
                    qa[1][0], qa[1][1], qa[1][2], qa[1][3], bb[0][2], bb[0][3]);
            mma_f16(d[nt][0], d[nt][1], d[nt][2], d[nt][3],
                    qa[2][0], qa[2][1], qa[2][2], qa[2][3], bb[1][0], bb[1][1]);
            mma_f16(d[nt][0], d[nt][1], d[nt][2], d[nt][3],
                    qa[3][0], qa[3][1], qa[3][2], qa[3][3], bb[1][2], bb[1][3]);
        }

        // ---- mask + exp + sco store + rowsum + pack P A-frags (in regs) ----
        unsigned pa[4];
        #pragma unroll
        for (int nt = 0; nt < 2; nt++) {
            float e0 = mc[nt].x     ? __expf(d[nt][0]) : 0.f;   // row gq
            float e1 = mc[nt].y     ? __expf(d[nt][1]) : 0.f;
            float e2 = mc[2 + nt].x ? __expf(d[nt][2]) : 0.f;   // row gq+8
            float e3 = mc[2 + nt].y ? __expf(d[nt][3]) : 0.f;
            *(__half2*)&sco[rowA * SSTR + jbase + nt * 8 + t2]       = __floats2half2_rn(e0, e1);
            *(__half2*)&sco[(rowA + 8) * SSTR + jbase + nt * 8 + t2] = __floats2half2_rn(e2, e3);
            rs0 += e0 + e1;
            rs1 += e2 + e3;
            pa[nt * 2]     = pk2f(e0, e1);   // a0/a2: row gq,   k nt*8+t2
            pa[nt * 2 + 1] = pk2f(e2, e3);   // a1/a3: row gq+8, k nt*8+t2
        }

        // ---- P @ V : V frags (hi only) + 8 mma into persistent acc ----
        const unsigned vb = sbase + OFF_V + (r & 1) * KVBUF_BYTES;
        #pragma unroll
        for (int cb = 0; cb < 4; cb++) {
            unsigned v0, v1, v2, v3;
            unsigned addr = vb +
                (unsigned)((jg * 16 + (lane & 15)) * KVSTR + cb * 16 + ((lane >> 4) & 1) * 8) * 2;
            ldsm_x4_t(v0, v1, v2, v3, addr);
            mma_f16(acc[cb * 2][0], acc[cb * 2][1], acc[cb * 2][2], acc[cb * 2][3],
                    pa[0], pa[1], pa[2], pa[3], v0, v1);
            mma_f16(acc[cb * 2 + 1][0], acc[cb * 2 + 1][1], acc[cb * 2 + 1][2], acc[cb * 2 + 1][3],
                    pa[0], pa[1], pa[2], pa[3], v2, v3);
        }
    }

    // ---- rowsum reduce ----
    rs0 += __shfl_xor_sync(0xffffffffu, rs0, 1);
    rs0 += __shfl_xor_sync(0xffffffffu, rs0, 2);
    rs1 += __shfl_xor_sync(0xffffffffu, rs1, 1);
    rs1 += __shfl_xor_sync(0xffffffffu, rs1, 2);
    if ((lane & 3) == 0) {
        red[w * 16 + gq]     = rs0;
        red[w * 16 + gq + 8] = rs1;
    }
    __syncthreads();
    if (t < 32) {
        int mbr = t >> 4, rl = t & 15;
        float s = 0.f;
        #pragma unroll
        for (int g = 0; g < 8; g++) s += red[(g * 2 + mbr) * 16 + rl];
        rinv[t] = 1.0f / s;
    }
    __syncthreads();

    // ---- normalized attn write (coalesced burst) ----
    #pragma unroll 4
    for (int i = 0; i < (M_TILE * T_SEQ / 4) / THREADS; i++) {   // 32
        int idx = i * THREADS + t;
        int rr = idx >> 9, cc = idx & 511;
        __half2 p0 = *(__half2*)&sco[rr * SSTR + cc * 4];
        __half2 p1 = *(__half2*)&sco[rr * SSTR + cc * 4 + 2];
        float ri = rinv[rr];
        float2 f0 = __half22float2(p0), f1 = __half22float2(p1);
        ((float4*)attng)[(size_t)rr * 512 + cc] =
            make_float4(f0.x * ri, f0.y * ri, f1.x * ri, f1.y * ri);
    }
    __syncthreads();   // all sco reads done -> safe to overwrite with partials

    // ---- cross-jg reduction of out partials (reuse sco region) ----
    float* part = (float*)(smc + OFF_SCO);   // [8 jg][32 rows][PSTR]
    #pragma unroll
    for (int nn = 0; nn < 8; nn++) {
        int col = nn * 8 + t2;
        *(float2*)&part[jg * (32 * PSTR) + rowA * PSTR + col] =
            make_float2(acc[nn][0], acc[nn][1]);
        *(float2*)&part[jg * (32 * PSTR) + (rowA + 8) * PSTR + col] =
            make_float2(acc[nn][2], acc[nn][3]);
    }
    __syncthreads();

    // 32 rows x 16 c4 = 512 float4: one per thread
    {
        int row = t >> 4, c4 = t & 15;
        float4 s = {0.f, 0.f, 0.f, 0.f};
        #pragma unroll
        for (int g = 0; g < 8; g++) {
            float4 p = *(float4*)&part[g * (32 * PSTR) + row * PSTR + c4 * 4];
            s.x += p.x; s.y += p.y; s.z += p.z; s.w += p.w;
        }
        float ri = rinv[row];
        s.x *= ri; s.y *= ri; s.z *= ri; s.w *= ri;
        ((float4*)outg)[row * 16 + c4] = s;
    }
}

extern "C" void kernel_launch(void* const* d_in, const int* in_sizes, int n_in,
                              void* d_out, int out_size)
{
    const float* q    = (const float*)d_in[0];
    const float* k    = (const float*)d_in[1];
    const float* v    = (const float*)d_in[2];
    const int*   mask = (const int*)d_in[3];

    float* out  = (float*)d_out;                                   // [B,H,T,C]
    float* attn = out + (size_t)BATCH * HEADS * T_SEQ * CDIM;      // [B,H,T,T]

    cudaFuncSetAttribute(sdpa_kernel,
                         cudaFuncAttributeMaxDynamicSharedMemorySize, SMEM_BYTES);

    dim3 grid(T_SEQ / M_TILE, HEADS, BATCH);   // (64, 16, 2)
    sdpa_kernel<<<grid, THREADS, SMEM_BYTES>>>(q, k, v, mask, out, attn);
}